// round 1
// baseline (speedup 1.0000x reference)
#include <cuda_runtime.h>

#define B_  2
#define T_  2048
#define HD  64
#define NH  8
#define DM  512
#define ED  512
#define EV  388

// ---------------- scratch (static device allocations are allowed) ----------
__device__ float g_qh [B_*T_*HD];
__device__ float g_kh [B_*T_*HD];
__device__ float g_vh [B_*T_*HD];
__device__ float g_ctx[B_*T_*DM];
__device__ float g_hid[B_*T_*ED];

#define FMA16(ACC, A4, B4) do { \
  ACC[0][0] = fmaf(A4.x, B4.x, ACC[0][0]); \
  ACC[0][1] = fmaf(A4.x, B4.y, ACC[0][1]); \
  ACC[0][2] = fmaf(A4.x, B4.z, ACC[0][2]); \
  ACC[0][3] = fmaf(A4.x, B4.w, ACC[0][3]); \
  ACC[1][0] = fmaf(A4.y, B4.x, ACC[1][0]); \
  ACC[1][1] = fmaf(A4.y, B4.y, ACC[1][1]); \
  ACC[1][2] = fmaf(A4.y, B4.z, ACC[1][2]); \
  ACC[1][3] = fmaf(A4.y, B4.w, ACC[1][3]); \
  ACC[2][0] = fmaf(A4.z, B4.x, ACC[2][0]); \
  ACC[2][1] = fmaf(A4.z, B4.y, ACC[2][1]); \
  ACC[2][2] = fmaf(A4.z, B4.z, ACC[2][2]); \
  ACC[2][3] = fmaf(A4.z, B4.w, ACC[2][3]); \
  ACC[3][0] = fmaf(A4.w, B4.x, ACC[3][0]); \
  ACC[3][1] = fmaf(A4.w, B4.y, ACC[3][1]); \
  ACC[3][2] = fmaf(A4.w, B4.z, ACC[3][2]); \
  ACC[3][3] = fmaf(A4.w, B4.w, ACC[3][3]); \
} while (0)

// ---------------- generic tiled GEMM: C = A[MxK] * B[KxN] + bias (opt relu) --
template<bool RELU>
__launch_bounds__(256)
__global__ void gemm_bias_kernel(const float* __restrict__ A, const float* __restrict__ Bm,
                                 const float* __restrict__ bias, float* __restrict__ C,
                                 int M, int N, int K) {
  __shared__ float As[16][68];   // k-major (transposed)
  __shared__ float Bs[16][64];
  const int tid = threadIdx.x;
  const int tx = tid & 15, ty = tid >> 4;
  const int m0 = blockIdx.x * 64, n0 = blockIdx.y * 64;
  float acc[4][4] = {};
  const int am  = tid >> 2, ak4 = (tid & 3) * 4;
  const int bk  = tid >> 4, bn4 = (tid & 15) * 4;
  for (int k0 = 0; k0 < K; k0 += 16) {
    float4 a4 = make_float4(0.f, 0.f, 0.f, 0.f);
    const int arow = m0 + am;
    if (arow < M) a4 = *(const float4*)(A + (size_t)arow * K + k0 + ak4);
    As[ak4 + 0][am] = a4.x; As[ak4 + 1][am] = a4.y;
    As[ak4 + 2][am] = a4.z; As[ak4 + 3][am] = a4.w;

    float4 b4 = make_float4(0.f, 0.f, 0.f, 0.f);
    const int bcol = n0 + bn4;
    const float* brow = Bm + (size_t)(k0 + bk) * N;
    if (bcol + 3 < N) {
      b4 = *(const float4*)(brow + bcol);
    } else {
      if (bcol + 0 < N) b4.x = brow[bcol + 0];
      if (bcol + 1 < N) b4.y = brow[bcol + 1];
      if (bcol + 2 < N) b4.z = brow[bcol + 2];
    }
    *(float4*)&Bs[bk][bn4] = b4;
    __syncthreads();
#pragma unroll
    for (int kk = 0; kk < 16; kk++) {
      float4 a = *(const float4*)&As[kk][ty * 4];
      float4 b = *(const float4*)&Bs[kk][tx * 4];
      FMA16(acc, a, b);
    }
    __syncthreads();
  }
#pragma unroll
  for (int i = 0; i < 4; i++) {
    const int row = m0 + ty * 4 + i;
    if (row >= M) continue;
#pragma unroll
    for (int j = 0; j < 4; j++) {
      const int col = n0 + tx * 4 + j;
      if (col >= N) continue;
      float v = acc[i][j] + bias[col];
      if (RELU) v = fmaxf(v, 0.f);
      C[(size_t)row * N + col] = v;
    }
  }
}

// ---------------- relative-bias chunk: QE[t][slot(r)] = q[t]·E[h,r], r in [cb,cb+64)
__device__ __forceinline__ void att_chunk(const float* __restrict__ E, const float* Qs,
                                          float* PE, float* QE, int h, int cb,
                                          int tx, int ty, int tid) {
  if (cb >= T_) return;   // uniform across block: only masked positions need r>=T
  for (int i = tid; i < 4096; i += 256) {
    const int j = i >> 6, dd = i & 63;
    PE[dd * 68 + j] = E[((size_t)(h * T_ + cb + j)) * HD + dd];
  }
  __syncthreads();
  float qe[4][4] = {};
#pragma unroll 8
  for (int dd = 0; dd < 64; dd++) {
    float4 a  = *(const float4*)&Qs[dd * 68 + ty * 4];
    float4 e4 = *(const float4*)&PE[dd * 68 + tx * 4];
    FMA16(qe, a, e4);
  }
#pragma unroll
  for (int i = 0; i < 4; i++)
#pragma unroll
    for (int j = 0; j < 4; j++)
      QE[(ty * 4 + i) * 132 + ((cb + tx * 4 + j) & 127)] = qe[i][j];
  __syncthreads();
}

// ---------------- flash attention with skewed relative bias ----------------
__launch_bounds__(256, 2)
__global__ void attn_kernel(const float* __restrict__ qh, const float* __restrict__ kh,
                            const float* __restrict__ vh, const float* __restrict__ E,
                            float* __restrict__ ctx) {
  extern __shared__ float sm[];
  float* Qs = sm;               // [64][68] dim-major: Qs[dd][t]
  float* Ks = Qs + 64 * 68;     // [64][68] dim-major: Ks[dd][s]
  float* Vs = Ks + 64 * 68;     // [64][68] s-major : Vs[e][c]
  float* PE = Vs + 64 * 68;     // [64][68] dual use: E chunk (dim-major) / P^T
  float* QE = PE + 64 * 68;     // [64][132] ring buffer of Q·E^T columns

  const int tid = threadIdx.x;
  const int tx = tid & 15, ty = tid >> 4;
  const int qt = (int)gridDim.x - 1 - (int)blockIdx.x;  // heavy tiles first
  const int t0 = qt * 64;
  const int b  = blockIdx.y;
  const int h  = blockIdx.z;

  // load Q tile (pre-scaled by 1/sqrt(hd); covers both QK and bias terms)
  for (int i = tid; i < 4096; i += 256) {
    const int d = i >> 6, dd = i & 63;
    Qs[dd * 68 + d] = qh[((size_t)(b * T_ + t0 + d)) * HD + dd] * 0.125f;
  }
  __syncthreads();

  const int wbase = T_ - 64 - t0;         // first r needed (64-aligned)
  att_chunk(E, Qs, PE, QE, h, wbase,      tx, ty, tid);
  att_chunk(E, Qs, PE, QE, h, wbase + 64, tx, ty, tid);

  float mrow[4], lrow[4], O[4][4];
#pragma unroll
  for (int i = 0; i < 4; i++) {
    mrow[i] = -1e30f; lrow[i] = 0.f;
#pragma unroll
    for (int j = 0; j < 4; j++) O[i][j] = 0.f;
  }

  const int nsteps = qt + 1;
  int cnext = wbase + 128;
  for (int it = 0; it < nsteps; it++) {
    const int s0 = it * 64;
    for (int i = tid; i < 4096; i += 256) {
      const int e = i >> 6, dd = i & 63;
      const size_t gidx = ((size_t)(b * T_ + s0 + e)) * HD + dd;
      Ks[dd * 68 + e] = kh[gidx];
      Vs[e * 68 + dd] = vh[gidx];
    }
    __syncthreads();

    // QK tile
    float acc[4][4] = {};
#pragma unroll 8
    for (int dd = 0; dd < 64; dd++) {
      float4 a  = *(const float4*)&Qs[dd * 68 + ty * 4];
      float4 k4 = *(const float4*)&Ks[dd * 68 + tx * 4];
      FMA16(acc, a, k4);
    }

    // add skewed relative bias + causal mask
    float rmax[4] = {-1e30f, -1e30f, -1e30f, -1e30f};
#pragma unroll
    for (int i = 0; i < 4; i++) {
      const int t = t0 + ty * 4 + i;
#pragma unroll
      for (int j = 0; j < 4; j++) {
        const int s = s0 + tx * 4 + j;
        float sc = -1e30f;
        if (s <= t) {
          const int r = s + (T_ - 1) - t;
          sc = acc[i][j] + QE[(ty * 4 + i) * 132 + (r & 127)];
        }
        acc[i][j] = sc;
        rmax[i] = fmaxf(rmax[i], sc);
      }
    }
    // row max across the 16 threads sharing each row (same half-warp)
#pragma unroll
    for (int i = 0; i < 4; i++) {
      rmax[i] = fmaxf(rmax[i], __shfl_xor_sync(0xffffffffu, rmax[i], 1));
      rmax[i] = fmaxf(rmax[i], __shfl_xor_sync(0xffffffffu, rmax[i], 2));
      rmax[i] = fmaxf(rmax[i], __shfl_xor_sync(0xffffffffu, rmax[i], 4));
      rmax[i] = fmaxf(rmax[i], __shfl_xor_sync(0xffffffffu, rmax[i], 8));
    }
    float psum[4];
#pragma unroll
    for (int i = 0; i < 4; i++) {
      const float mnew  = fmaxf(mrow[i], rmax[i]);
      const float alpha = __expf(mrow[i] - mnew);
      mrow[i] = mnew;
      float s4 = 0.f;
#pragma unroll
      for (int j = 0; j < 4; j++) {
        const float p = __expf(acc[i][j] - mnew);   // masked -1e30 -> exp = 0
        acc[i][j] = p;
        s4 += p;
      }
      psum[i] = s4;
      lrow[i] *= alpha;
#pragma unroll
      for (int j = 0; j < 4; j++) O[i][j] *= alpha;
    }
#pragma unroll
    for (int i = 0; i < 4; i++) {
      psum[i] += __shfl_xor_sync(0xffffffffu, psum[i], 1);
      psum[i] += __shfl_xor_sync(0xffffffffu, psum[i], 2);
      psum[i] += __shfl_xor_sync(0xffffffffu, psum[i], 4);
      psum[i] += __shfl_xor_sync(0xffffffffu, psum[i], 8);
      lrow[i] += psum[i];
    }
    // write P^T for the PV GEMM
#pragma unroll
    for (int i = 0; i < 4; i++)
#pragma unroll
      for (int j = 0; j < 4; j++)
        PE[(tx * 4 + j) * 68 + ty * 4 + i] = acc[i][j];
    __syncthreads();
#pragma unroll 8
    for (int e = 0; e < 64; e++) {
      float4 p  = *(const float4*)&PE[e * 68 + ty * 4];
      float4 v4 = *(const float4*)&Vs[e * 68 + tx * 4];
      FMA16(O, p, v4);
    }
    __syncthreads();
    if (it + 1 < nsteps) { att_chunk(E, Qs, PE, QE, h, cnext, tx, ty, tid); cnext += 64; }
  }

  // epilogue: normalized, head-concatenated layout [B,T,H*hd]
#pragma unroll
  for (int i = 0; i < 4; i++) {
    const int t = t0 + ty * 4 + i;
    const float inv = 1.f / lrow[i];
    float4 o4 = make_float4(O[i][0] * inv, O[i][1] * inv, O[i][2] * inv, O[i][3] * inv);
    *(float4*)&ctx[((size_t)(b * T_ + t)) * DM + h * HD + tx * 4] = o4;
  }
}

// ---------------------------------------------------------------------------
extern "C" void kernel_launch(void* const* d_in, const int* in_sizes, int n_in,
                              void* d_out, int out_size) {
  const float* v  = (const float*)d_in[0];
  const float* k  = (const float*)d_in[1];
  const float* q  = (const float*)d_in[2];
  // d_in[3] = mask (causal tril; implicit in kernel)
  const float* Wq = (const float*)d_in[4];
  const float* bq = (const float*)d_in[5];
  const float* Wk = (const float*)d_in[6];
  const float* bk = (const float*)d_in[7];
  const float* Wv = (const float*)d_in[8];
  const float* bv = (const float*)d_in[9];
  const float* E  = (const float*)d_in[10];
  const float* Wo = (const float*)d_in[11];
  const float* bo = (const float*)d_in[12];
  const float* Wl = (const float*)d_in[13];
  const float* bl = (const float*)d_in[14];
  float* out = (float*)d_out;

  float *qh, *kh, *vh, *ctx, *hid;
  cudaGetSymbolAddress((void**)&qh,  g_qh);
  cudaGetSymbolAddress((void**)&kh,  g_kh);
  cudaGetSymbolAddress((void**)&vh,  g_vh);
  cudaGetSymbolAddress((void**)&ctx, g_ctx);
  cudaGetSymbolAddress((void**)&hid, g_hid);

  const int M = B_ * T_;
  dim3 blk(256);

  gemm_bias_kernel<false><<<dim3(M / 64, 1), blk>>>(q, Wq, bq, qh, M, HD, DM);
  gemm_bias_kernel<false><<<dim3(M / 64, 1), blk>>>(k, Wk, bk, kh, M, HD, DM);
  gemm_bias_kernel<false><<<dim3(M / 64, 1), blk>>>(v, Wv, bv, vh, M, HD, DM);

  const size_t ATT_SMEM = (size_t)(4 * 64 * 68 + 64 * 132) * sizeof(float); // 103424 B
  cudaFuncSetAttribute(attn_kernel, cudaFuncAttributeMaxDynamicSharedMemorySize,
                       (int)ATT_SMEM);
  attn_kernel<<<dim3(T_ / 64, B_, NH), blk, ATT_SMEM>>>(qh, kh, vh, E, ctx);

  gemm_bias_kernel<true ><<<dim3(M / 64, ED / 64), blk>>>(ctx, Wo, bo, hid, M, ED, DM);
  gemm_bias_kernel<false><<<dim3(M / 64, (EV + 63) / 64), blk>>>(hid, Wl, bl, out, M, EV, ED);
}